// round 3
// baseline (speedup 1.0000x reference)
#include <cuda_runtime.h>
#include <math.h>

#define TOK  16384
#define HID  4096
#define NE   64
#define CTOP 512
#define EPSF 1e-6f
#define BM 64
#define BK 32
#define NT (HID / BK)

__device__ float g_logits[TOK * NE];
__device__ float g_part[(TOK / 8) * NE];

#define FMA2(d, a, b) asm("fma.rn.f32x2 %0, %1, %2, %0;" : "+l"(d) : "l"(a), "l"(b))

// swizzles: slot in [0,8) of 16B chunks within a 32-float row
__device__ __forceinline__ int swzA(int r) { return ((r >> 2) & 7) ^ (r & 3); }
__device__ __forceinline__ int swzB(int r) { return ((r >> 3) & 7) ^ (r & 7); }

// ---------------- GEMM: logits = hidden @ gate_w^T (fp32, FFMA2 K-packed) ---
__global__ void __launch_bounds__(128)
gemm_kernel(const float* __restrict__ A, const float* __restrict__ B)
{
    __shared__ __align__(16) float As[2][BM * BK];
    __shared__ __align__(16) float Bs[2][NE * BK];
    const int tid = threadIdx.x;
    const int bm0 = blockIdx.x * BM;
    const int lr = tid >> 3, lk = tid & 7;   // loader coords
    const int tg = tid >> 3, eg = tid & 7;   // compute coords

    const float4 *Ag[4], *Bg[4];
    int ao[4], bo[4];
#pragma unroll
    for (int j = 0; j < 4; j++) {
        const int r = lr + 16 * j;
        Ag[j] = reinterpret_cast<const float4*>(A + (size_t)(bm0 + r) * HID) + lk;
        Bg[j] = reinterpret_cast<const float4*>(B + (size_t)r * HID) + lk;
        ao[j] = r * BK + ((lk ^ swzA(r)) << 2);
        bo[j] = r * BK + ((lk ^ swzB(r)) << 2);
    }

    unsigned long long acc[4][8];
#pragma unroll
    for (int t = 0; t < 4; t++)
#pragma unroll
        for (int e = 0; e < 8; e++) acc[t][e] = 0ull;

    float4 ra[4], rb[4];
#pragma unroll
    for (int j = 0; j < 4; j++) { ra[j] = Ag[j][0]; rb[j] = Bg[j][0]; }
#pragma unroll
    for (int j = 0; j < 4; j++) {
        *reinterpret_cast<float4*>(&As[0][ao[j]]) = ra[j];
        *reinterpret_cast<float4*>(&Bs[0][bo[j]]) = rb[j];
    }
    __syncthreads();

    for (int kt = 0; kt < NT; kt++) {
        const int buf = kt & 1;
        if (kt + 1 < NT) {
#pragma unroll
            for (int j = 0; j < 4; j++) {
                ra[j] = Ag[j][(kt + 1) * (BK / 4)];
                rb[j] = Bg[j][(kt + 1) * (BK / 4)];
            }
        }
#pragma unroll
        for (int kc = 0; kc < BK / 4; kc++) {
            ulonglong2 av[4], bv[8];
#pragma unroll
            for (int t = 0; t < 4; t++) {
                const int r = 4 * tg + t;
                av[t] = *reinterpret_cast<const ulonglong2*>(
                    &As[buf][r * BK + ((kc ^ swzA(r)) << 2)]);
            }
#pragma unroll
            for (int e = 0; e < 8; e++) {
                const int r = 8 * eg + e;
                bv[e] = *reinterpret_cast<const ulonglong2*>(
                    &Bs[buf][r * BK + ((kc ^ swzB(r)) << 2)]);
            }
#pragma unroll
            for (int t = 0; t < 4; t++)
#pragma unroll
                for (int e = 0; e < 8; e++) {
                    FMA2(acc[t][e], av[t].x, bv[e].x);
                    FMA2(acc[t][e], av[t].y, bv[e].y);
                }
        }
        if (kt + 1 < NT) {
            const int nb = (kt + 1) & 1;
#pragma unroll
            for (int j = 0; j < 4; j++) {
                *reinterpret_cast<float4*>(&As[nb][ao[j]]) = ra[j];
                *reinterpret_cast<float4*>(&Bs[nb][bo[j]]) = rb[j];
            }
        }
        __syncthreads();
    }

#pragma unroll
    for (int t = 0; t < 4; t++) {
        float v[8];
#pragma unroll
        for (int e = 0; e < 8; e++) {
            const unsigned long long u = acc[t][e];
            v[e] = __uint_as_float((unsigned)(u & 0xffffffffull)) +
                   __uint_as_float((unsigned)(u >> 32));
        }
        float4* dst = reinterpret_cast<float4*>(
            &g_logits[(bm0 + 4 * tg + t) * NE + 8 * eg]);
        dst[0] = make_float4(v[0], v[1], v[2], v[3]);
        dst[1] = make_float4(v[4], v[5], v[6], v[7]);
    }
}

// ---------------- top-C per expert: 8-bit radix select, ties by low index ---
__device__ __forceinline__ unsigned omap(float f) {
    unsigned u = __float_as_uint(f);
    return (u & 0x80000000u) ? ~u : (u | 0x80000000u);
}

__global__ void __launch_bounds__(256)
topk_kernel(float* __restrict__ routing)
{
    __shared__ unsigned hist[256];
    __shared__ unsigned tlist[256];
    __shared__ unsigned s_pref, s_rem, s_tc;
    const int e = blockIdx.x, tid = threadIdx.x;
    if (tid == 0) { s_pref = 0u; s_rem = CTOP; s_tc = 0u; }

    for (int b = 3; b >= 0; b--) {
        __syncthreads();
        hist[tid] = 0u;
        __syncthreads();
        const unsigned pref = s_pref;
        for (int t = tid; t < TOK; t += 256) {
            const unsigned u = omap(g_logits[t * NE + e]);
            const bool ok = (b == 3) || ((u >> (((b + 1) & 3) * 8)) == pref);
            if (ok) atomicAdd(&hist[(u >> (b * 8)) & 255u], 1u);
        }
        __syncthreads();
        if (tid == 0) {
            unsigned rem = s_rem, cum = 0u;
            int d = 255;
            for (; d > 0; d--) { cum += hist[d]; if (cum >= rem) break; }
            if (cum < rem) { cum += hist[0]; d = 0; }
            s_rem = rem - (cum - hist[d]);
            s_pref = (pref << 8) | (unsigned)d;
        }
    }
    __syncthreads();
    const unsigned tkey = s_pref;
    for (int t = tid; t < TOK; t += 256) {
        const unsigned u = omap(g_logits[t * NE + e]);
        float r = 0.f;
        if (u > tkey) r = 1.f;
        else if (u == tkey) {
            const unsigned p = atomicAdd(&s_tc, 1u);
            if (p < 256u) tlist[p] = (unsigned)t;
        }
        routing[(size_t)t * NE + e] = r;
    }
    __syncthreads();
    if (tid == 0) {
        int n = (int)s_tc; if (n > 256) n = 256;
        for (int i = 1; i < n; i++) {                 // insertion sort (n tiny)
            const unsigned v = tlist[i]; int j = i - 1;
            while (j >= 0 && tlist[j] > v) { tlist[j + 1] = tlist[j]; j--; }
            tlist[j + 1] = v;
        }
        int take = (int)s_rem; if (take > n) take = n;
        for (int i = 0; i < take; i++)
            routing[(size_t)tlist[i] * NE + e] = 1.f;
    }
}

// ---------------- softmax + mask + renorm; deterministic block partials -----
__global__ void __launch_bounds__(256)
softmax_kernel(const float* __restrict__ routing, float* __restrict__ probs)
{
    const int lane = threadIdx.x & 31, w = threadIdx.x >> 5;
    const int t = blockIdx.x * 8 + w;
    __shared__ float sA[8][32], sB[8][32];

    const float l0 = g_logits[t * NE + lane];
    const float l1 = g_logits[t * NE + 32 + lane];
    float m = fmaxf(l0, l1);
#pragma unroll
    for (int o = 16; o; o >>= 1) m = fmaxf(m, __shfl_xor_sync(~0u, m, o));
    const float e0 = __expf(l0 - m), e1 = __expf(l1 - m);
    float s = e0 + e1;
#pragma unroll
    for (int o = 16; o; o >>= 1) s += __shfl_xor_sync(~0u, s, o);
    const float q0 = (e0 / s) * routing[(size_t)t * NE + lane];
    const float q1 = (e1 / s) * routing[(size_t)t * NE + 32 + lane];
    float rs = q0 + q1;
#pragma unroll
    for (int o = 16; o; o >>= 1) rs += __shfl_xor_sync(~0u, rs, o);
    const float inv = 1.f / (rs + EPSF);
    const float n0 = q0 * inv, n1 = q1 * inv;
    probs[(size_t)t * NE + lane] = n0;
    probs[(size_t)t * NE + 32 + lane] = n1;

    sA[w][lane] = n0; sB[w][lane] = n1;
    __syncthreads();
    if (w == 0) {
        float a = 0.f;
#pragma unroll
        for (int k = 0; k < 8; k++) a += sA[k][lane];
        g_part[blockIdx.x * NE + lane] = a;
    } else if (w == 1) {
        float a = 0.f;
#pragma unroll
        for (int k = 0; k < 8; k++) a += sB[k][lane];
        g_part[blockIdx.x * NE + 32 + lane] = a;
    }
}

// ---------------- aux loss (load_loss == 0 by construction) -----------------
__global__ void __launch_bounds__(256)
aux_kernel(float* __restrict__ aux)
{
    __shared__ float tmp[4][64];
    __shared__ float imp[64];
    const int tid = threadIdx.x;           // 256
    const int e = tid & 63, p = tid >> 6;  // p: 0..3
    float s = 0.f;
    for (int i = p; i < TOK / 8; i += 4) s += g_part[i * NE + e];
    tmp[p][e] = s;
    __syncthreads();
    if (tid < 64) {
        float a = 0.f;
#pragma unroll
        for (int k = 0; k < 4; k++) a += tmp[k][tid];
        imp[tid] = a;
    }
    __syncthreads();
    if (tid == 0) {
        float m = 0.f;
        for (int i = 0; i < 64; i++) m += imp[i];
        m *= (1.f / 64.f);
        float v = 0.f;
        for (int i = 0; i < 64; i++) { const float d = imp[i] - m; v += d * d; }
        v *= (1.f / 63.f);
        const float r = sqrtf(v) / (m + EPSF);
        aux[0] = r * r;    // load std == 0 exactly -> load_loss == 0
    }
}

extern "C" void kernel_launch(void* const* d_in, const int* in_sizes, int n_in,
                              void* d_out, int out_size)
{
    const float* hidden = (const float*)d_in[0];
    const float* gate   = (const float*)d_in[1];
    float* probs   = (float*)d_out;
    float* routing = probs + (size_t)TOK * NE;
    float* aux     = routing + (size_t)TOK * NE;

    gemm_kernel<<<TOK / BM, 128>>>(hidden, gate);
    topk_kernel<<<NE, 256>>>(routing);
    softmax_kernel<<<TOK / 8, 256>>>(routing, probs);
    aux_kernel<<<1, 256>>>(aux);
}

// round 5
// speedup vs baseline: 1.7056x; 1.7056x over previous
#include <cuda_runtime.h>
#include <cuda_fp16.h>
#include <math.h>
#include <cstdint>

#define TOK  16384
#define HID  4096
#define NE   64
#define CTOP 512
#define EPSF 1e-6f

#define BM   128
#define KC   32
#define NT   (HID / KC)      // 128 k-chunks
#define PITCH 40             // halfs per smem row (32 data + 8 pad)

// smem layout per buffer (in halfs): Ah[128*40] Al[128*40] Bh[64*40] Bl[64*40]
#define AH_OFF 0
#define AL_OFF (128 * PITCH)
#define BH_OFF (256 * PITCH)
#define BL_OFF (320 * PITCH)
#define BUFH   (384 * PITCH)          // 15360 halfs per buffer
#define SMEMSZ (2 * BUFH * 2)         // bytes = 61440

__device__ float g_logits[TOK * NE];
__device__ float g_part[(TOK / 8) * NE];
__device__ float g_imp[NE];

// ---------------------------- PTX helpers -----------------------------------
__device__ __forceinline__ uint32_t smem_u32(const void* p) {
    uint32_t a;
    asm("{ .reg .u64 t; cvta.to.shared.u64 t, %1; cvt.u32.u64 %0, t; }"
        : "=r"(a) : "l"(p));
    return a;
}
__device__ __forceinline__ void ldsm4(uint32_t* r, uint32_t addr) {
    asm volatile("ldmatrix.sync.aligned.m8n8.x4.shared.b16 {%0,%1,%2,%3}, [%4];"
                 : "=r"(r[0]), "=r"(r[1]), "=r"(r[2]), "=r"(r[3]) : "r"(addr));
}
__device__ __forceinline__ void mma16816(float* c, const uint32_t* a,
                                         const uint32_t* b) {
    asm volatile(
        "mma.sync.aligned.m16n8k16.row.col.f32.f16.f16.f32 "
        "{%0,%1,%2,%3}, {%4,%5,%6,%7}, {%8,%9}, {%0,%1,%2,%3};"
        : "+f"(c[0]), "+f"(c[1]), "+f"(c[2]), "+f"(c[3])
        : "r"(a[0]), "r"(a[1]), "r"(a[2]), "r"(a[3]), "r"(b[0]), "r"(b[1]));
}
__device__ __forceinline__ void split_f4(float4 v, uint2& h, uint2& l) {
    __half2 a = __floats2half2_rn(v.x, v.y);
    __half2 b = __floats2half2_rn(v.z, v.w);
    float2 af = __half22float2(a), bf = __half22float2(b);
    __half2 c = __floats2half2_rn(v.x - af.x, v.y - af.y);
    __half2 d = __floats2half2_rn(v.z - bf.x, v.w - bf.y);
    h.x = *reinterpret_cast<uint32_t*>(&a); h.y = *reinterpret_cast<uint32_t*>(&b);
    l.x = *reinterpret_cast<uint32_t*>(&c); l.y = *reinterpret_cast<uint32_t*>(&d);
}

// ============ GEMM: logits = hidden @ gate_w^T  (3xFP16 mma.sync) ===========
__global__ void __launch_bounds__(256, 1)
gemm_kernel(const float* __restrict__ A, const float* __restrict__ B)
{
    extern __shared__ __half sm[];
    const int tid = threadIdx.x, lane = tid & 31, wid = tid >> 5;
    const int bm0 = blockIdx.x * BM;

    // ldg assignments
    const int ar = tid >> 2, ac = tid & 3;          // A: rows ar, ar+64; f4 cols ac, ac+4
    const int br = tid >> 2, bc = tid & 3;          // B: row br;        f4 cols bc, bc+4
    const float4* Agp = reinterpret_cast<const float4*>(A);
    const float4* Bgp = reinterpret_cast<const float4*>(B);

    // sts half-offsets (within a buffer)
    const int stsA0 = ar * PITCH + ac * 4;          // +64*PITCH for row+64; +16 for col+4
    const int stsB0 = br * PITCH + bc * 4;

    // ldmatrix per-thread byte offsets (within a buffer)
    const uint32_t smb = smem_u32(sm);
    const int a_row = wid * 16 + (lane & 15);
    const int a_k   = (lane >> 4) << 3;
    const uint32_t lmA = (uint32_t)((a_row * PITCH + a_k) * 2);
    const int b_n = (lane & 7) + ((lane >> 4) << 3);
    const int b_k = lane & 8;
    const uint32_t lmB = (uint32_t)((b_n * PITCH + b_k) * 2);

    float acc[8][4];
#pragma unroll
    for (int n = 0; n < 8; n++)
#pragma unroll
        for (int i = 0; i < 4; i++) acc[n][i] = 0.f;

    float4 ra[4], rb[2];
    // prologue: load kt=0, store to buffer 0
#pragma unroll
    for (int j = 0; j < 4; j++)
        ra[j] = Agp[(size_t)(bm0 + ar + 64 * (j >> 1)) * (HID / 4) + ((j & 1) ? ac + 4 : ac)];
#pragma unroll
    for (int j = 0; j < 2; j++)
        rb[j] = Bgp[(size_t)br * (HID / 4) + (j ? bc + 4 : bc)];
    {
        __half* buf = sm;
#pragma unroll
        for (int j = 0; j < 4; j++) {
            uint2 h, l; split_f4(ra[j], h, l);
            const int o = stsA0 + 64 * PITCH * (j >> 1) + ((j & 1) << 4);
            *reinterpret_cast<uint2*>(buf + AH_OFF + o) = h;
            *reinterpret_cast<uint2*>(buf + AL_OFF + o) = l;
        }
#pragma unroll
        for (int j = 0; j < 2; j++) {
            uint2 h, l; split_f4(rb[j], h, l);
            const int o = stsB0 + (j << 4);
            *reinterpret_cast<uint2*>(buf + BH_OFF + o) = h;
            *reinterpret_cast<uint2*>(buf + BL_OFF + o) = l;
        }
    }
    __syncthreads();

#pragma unroll 1
    for (int kt = 0; kt < NT; kt++) {
        // prefetch kt+1
        if (kt + 1 < NT) {
            const int kofs = (kt + 1) * (KC / 4);
#pragma unroll
            for (int j = 0; j < 4; j++)
                ra[j] = Agp[(size_t)(bm0 + ar + 64 * (j >> 1)) * (HID / 4) + kofs + ((j & 1) ? ac + 4 : ac)];
#pragma unroll
            for (int j = 0; j < 2; j++)
                rb[j] = Bgp[(size_t)br * (HID / 4) + kofs + (j ? bc + 4 : bc)];
        }
        // MMA on buffer kt&1
        const uint32_t bb = smb + (uint32_t)((kt & 1) * BUFH * 2);
#pragma unroll
        for (int ks = 0; ks < 2; ks++) {
            uint32_t ah[4], al[4], bh[16], bl[16];
            ldsm4(ah, bb + AH_OFF * 2 + lmA + ks * 32);
            ldsm4(al, bb + AL_OFF * 2 + lmA + ks * 32);
#pragma unroll
            for (int p = 0; p < 4; p++) {
                ldsm4(bh + 4 * p, bb + BH_OFF * 2 + lmB + ks * 32 + p * 16 * PITCH * 2);
                ldsm4(bl + 4 * p, bb + BL_OFF * 2 + lmB + ks * 32 + p * 16 * PITCH * 2);
            }
#pragma unroll
            for (int n = 0; n < 8; n++) {
                const int bi = (n >> 1) * 4 + (n & 1) * 2;
                mma16816(acc[n], ah, bh + bi);   // hi*hi
                mma16816(acc[n], ah, bl + bi);   // hi*lo
                mma16816(acc[n], al, bh + bi);   // lo*hi
            }
        }
        if (kt + 1 < NT) {
            __syncthreads();
            __half* buf = sm + ((kt + 1) & 1) * BUFH;
#pragma unroll
            for (int j = 0; j < 4; j++) {
                uint2 h, l; split_f4(ra[j], h, l);
                const int o = stsA0 + 64 * PITCH * (j >> 1) + ((j & 1) << 4);
                *reinterpret_cast<uint2*>(buf + AH_OFF + o) = h;
                *reinterpret_cast<uint2*>(buf + AL_OFF + o) = l;
            }
#pragma unroll
            for (int j = 0; j < 2; j++) {
                uint2 h, l; split_f4(rb[j], h, l);
                const int o = stsB0 + (j << 4);
                *reinterpret_cast<uint2*>(buf + BH_OFF + o) = h;
                *reinterpret_cast<uint2*>(buf + BL_OFF + o) = l;
            }
            __syncthreads();
        }
    }

    // epilogue: acc[n][0..1] -> row gid, cols n*8+(lane&3)*2 ; acc[n][2..3] -> row gid+8
    const int gid = lane >> 2;
    const int col = (lane & 3) * 2;
    const int row0 = bm0 + wid * 16 + gid;
#pragma unroll
    for (int n = 0; n < 8; n++) {
        *reinterpret_cast<float2*>(&g_logits[row0 * NE + n * 8 + col]) =
            make_float2(acc[n][0], acc[n][1]);
        *reinterpret_cast<float2*>(&g_logits[(row0 + 8) * NE + n * 8 + col]) =
            make_float2(acc[n][2], acc[n][3]);
    }
}

// ===================== top-C per expert (radix select, tie by low idx) ======
__device__ __forceinline__ unsigned omap(float f) {
    unsigned u = __float_as_uint(f);
    return (u & 0x80000000u) ? ~u : (u | 0x80000000u);
}
__global__ void __launch_bounds__(256)
topk_kernel(float* __restrict__ routing)
{
    __shared__ unsigned hist[256];
    __shared__ unsigned tlist[256];
    __shared__ unsigned s_pref, s_rem, s_tc;
    const int e = blockIdx.x, tid = threadIdx.x;
    if (tid == 0) { s_pref = 0u; s_rem = CTOP; s_tc = 0u; }
    for (int b = 3; b >= 0; b--) {
        __syncthreads();
        hist[tid] = 0u;
        __syncthreads();
        const unsigned pref = s_pref;
        for (int t = tid; t < TOK; t += 256) {
            const unsigned u = omap(g_logits[t * NE + e]);
            const bool ok = (b == 3) || ((u >> (((b + 1) & 3) * 8)) == pref);
            if (ok) atomicAdd(&hist[(u >> (b * 8)) & 255u], 1u);
        }
        __syncthreads();
        if (tid == 0) {
            unsigned rem = s_rem, cum = 0u;
            int d = 255;
            for (; d > 0; d--) { cum += hist[d]; if (cum >= rem) break; }
            if (cum < rem) { cum += hist[0]; d = 0; }
            s_rem = rem - (cum - hist[d]);
            s_pref = (pref << 8) | (unsigned)d;
        }
    }
    __syncthreads();
    const unsigned tkey = s_pref;
    for (int t = tid; t < TOK; t += 256) {
        const unsigned u = omap(g_logits[t * NE + e]);
        float r = 0.f;
        if (u > tkey) r = 1.f;
        else if (u == tkey) {
            const unsigned p = atomicAdd(&s_tc, 1u);
            if (p < 256u) tlist[p] = (unsigned)t;
        }
        routing[(size_t)t * NE + e] = r;
    }
    __syncthreads();
    if (tid == 0) {
        int n = (int)s_tc; if (n > 256) n = 256;
        for (int i = 1; i < n; i++) {
            const unsigned v = tlist[i]; int j = i - 1;
            while (j >= 0 && tlist[j] > v) { tlist[j + 1] = tlist[j]; j--; }
            tlist[j + 1] = v;
        }
        int take = (int)s_rem; if (take > n) take = n;
        for (int i = 0; i < take; i++)
            routing[(size_t)tlist[i] * NE + e] = 1.f;
    }
}

// ============ softmax + mask + renorm; deterministic block partials =========
__global__ void __launch_bounds__(256)
softmax_kernel(const float* __restrict__ routing, float* __restrict__ probs)
{
    const int lane = threadIdx.x & 31, w = threadIdx.x >> 5;
    const int t = blockIdx.x * 8 + w;
    __shared__ float sA[8][32], sB[8][32];

    const float l0 = g_logits[t * NE + lane];
    const float l1 = g_logits[t * NE + 32 + lane];
    float m = fmaxf(l0, l1);
#pragma unroll
    for (int o = 16; o; o >>= 1) m = fmaxf(m, __shfl_xor_sync(~0u, m, o));
    const float e0 = __expf(l0 - m), e1 = __expf(l1 - m);
    float s = e0 + e1;
#pragma unroll
    for (int o = 16; o; o >>= 1) s += __shfl_xor_sync(~0u, s, o);
    const float q0 = (e0 / s) * routing[(size_t)t * NE + lane];
    const float q1 = (e1 / s) * routing[(size_t)t * NE + 32 + lane];
    float rs = q0 + q1;
#pragma unroll
    for (int o = 16; o; o >>= 1) rs += __shfl_xor_sync(~0u, rs, o);
    const float inv = 1.f / (rs + EPSF);
    const float n0 = q0 * inv, n1 = q1 * inv;
    probs[(size_t)t * NE + lane] = n0;
    probs[(size_t)t * NE + 32 + lane] = n1;

    sA[w][lane] = n0; sB[w][lane] = n1;
    __syncthreads();
    if (w == 0) {
        float a = 0.f;
#pragma unroll
        for (int k = 0; k < 8; k++) a += sA[k][lane];
        g_part[blockIdx.x * NE + lane] = a;
    } else if (w == 1) {
        float a = 0.f;
#pragma unroll
        for (int k = 0; k < 8; k++) a += sB[k][lane];
        g_part[blockIdx.x * NE + 32 + lane] = a;
    }
}

// ===================== aux loss (parallel importance reduce) ================
__global__ void __launch_bounds__(256)
imp_kernel()
{
    __shared__ float red[8];
    const int e = blockIdx.x, tid = threadIdx.x;
    float s = 0.f;
    for (int i = tid; i < TOK / 8; i += 256) s += g_part[i * NE + e];
#pragma unroll
    for (int o = 16; o; o >>= 1) s += __shfl_xor_sync(~0u, s, o);
    if ((tid & 31) == 0) red[tid >> 5] = s;
    __syncthreads();
    if (tid == 0) {
        float a = 0.f;
#pragma unroll
        for (int k = 0; k < 8; k++) a += red[k];
        g_imp[e] = a;
    }
}
__global__ void __launch_bounds__(64)
loss_kernel(float* __restrict__ aux)
{
    __shared__ float v[64];
    v[threadIdx.x] = g_imp[threadIdx.x];
    __syncthreads();
    if (threadIdx.x == 0) {
        float m = 0.f;
        for (int i = 0; i < 64; i++) m += v[i];
        m *= (1.f / 64.f);
        float var = 0.f;
        for (int i = 0; i < 64; i++) { const float d = v[i] - m; var += d * d; }
        var *= (1.f / 63.f);
        const float r = sqrtf(var) / (m + EPSF);
        aux[0] = r * r;   // load std == 0 exactly -> load_loss == 0
    }
}

extern "C" void kernel_launch(void* const* d_in, const int* in_sizes, int n_in,
                              void* d_out, int out_size)
{
    const float* hidden = (const float*)d_in[0];
    const float* gate   = (const float*)d_in[1];
    float* probs   = (float*)d_out;
    float* routing = probs + (size_t)TOK * NE;
    float* aux     = routing + (size_t)TOK * NE;

    cudaFuncSetAttribute(gemm_kernel,
                         cudaFuncAttributeMaxDynamicSharedMemorySize, SMEMSZ);
    gemm_kernel<<<TOK / BM, 256, SMEMSZ>>>(hidden, gate);
    topk_kernel<<<NE, 256>>>(routing);
    softmax_kernel<<<TOK / 8, 256>>>(routing, probs);
    imp_kernel<<<NE, 256>>>();
    loss_kernel<<<1, 64>>>(aux);
}

// round 6
// speedup vs baseline: 1.8812x; 1.1029x over previous
#include <cuda_runtime.h>
#include <cuda_fp16.h>
#include <math.h>
#include <cstdint>

#define TOK  16384
#define HID  4096
#define NE   64
#define CTOP 512
#define EPSF 1e-6f

#define BM   128
#define NKT  (HID / 32)          // 128 k32 chunks
#define NPART 2048               // softmax blocks

__device__ float g_logits[TOK * NE];
__device__ float g_partT[NE * NPART];   // transposed partials [e][blk]
__device__ float g_imp[NE];
__device__ uint4 g_bfrag[256 * 8 * 32]; // [k16][n8][lane] = {b0h,b1h,b0l,b1l}

// ---------------------------- helpers ---------------------------------------
__device__ __forceinline__ void mma16816(float* c, const uint32_t* a,
                                         const uint32_t* b) {
    asm volatile(
        "mma.sync.aligned.m16n8k16.row.col.f32.f16.f16.f32 "
        "{%0,%1,%2,%3}, {%4,%5,%6,%7}, {%8,%9}, {%0,%1,%2,%3};"
        : "+f"(c[0]), "+f"(c[1]), "+f"(c[2]), "+f"(c[3])
        : "r"(a[0]), "r"(a[1]), "r"(a[2]), "r"(a[3]), "r"(b[0]), "r"(b[1]));
}
__device__ __forceinline__ void split_f2(float2 v, uint32_t& h, uint32_t& l) {
    __half2 hh = __floats2half2_rn(v.x, v.y);
    float2 hf = __half22float2(hh);
    __half2 ll = __floats2half2_rn(v.x - hf.x, v.y - hf.y);
    h = *reinterpret_cast<uint32_t*>(&hh);
    l = *reinterpret_cast<uint32_t*>(&ll);
}

// ------------- pre-kernel: gate_w -> fragment-replicated hi/lo halves -------
__global__ void __launch_bounds__(256)
build_bfrag(const float* __restrict__ gate)
{
    const int idx = blockIdx.x * 256 + threadIdx.x;  // 65536 total
    const int lane = idx & 31, n8 = (idx >> 5) & 7, k16 = idx >> 8;
    const int n = n8 * 8 + (lane >> 2);
    const int k0 = k16 * 16 + (lane & 3) * 2;
    const float* g = gate + (size_t)n * HID + k0;
    const float2 v0 = *reinterpret_cast<const float2*>(g);
    const float2 v1 = *reinterpret_cast<const float2*>(g + 8);
    uint32_t b0h, b0l, b1h, b1l;
    split_f2(v0, b0h, b0l);
    split_f2(v1, b1h, b1l);
    g_bfrag[idx] = make_uint4(b0h, b1h, b0l, b1l);
}

// ======= GEMM: logits = hidden @ gate_w^T (3xFP16 mma, smem-free) ===========
__global__ void __launch_bounds__(256, 1)
gemm_kernel(const float* __restrict__ A)
{
    const int tid = threadIdx.x, lane = tid & 31, wid = tid >> 5;
    const int bm0 = blockIdx.x * BM;
    const int row = bm0 + wid * 16 + (lane >> 2);

    const float* a0 = A + (size_t)row * HID + (lane & 3) * 2;
    const float* a1 = a0 + 8 * HID;

    float acc[8][4];
#pragma unroll
    for (int n = 0; n < 8; n++)
#pragma unroll
        for (int i = 0; i < 4; i++) acc[n][i] = 0.f;

    // prefetch kt=0 raw A (8 float2: [ks][pos])
    float2 cur[8], nxt[8];
#pragma unroll
    for (int ks = 0; ks < 2; ks++) {
        const int o = ks * 16;
        cur[ks * 4 + 0] = *reinterpret_cast<const float2*>(a0 + o);
        cur[ks * 4 + 1] = *reinterpret_cast<const float2*>(a1 + o);
        cur[ks * 4 + 2] = *reinterpret_cast<const float2*>(a0 + o + 8);
        cur[ks * 4 + 3] = *reinterpret_cast<const float2*>(a1 + o + 8);
    }

#pragma unroll 1
    for (int kt = 0; kt < NKT; kt++) {
        if (kt + 1 < NKT) {
            const int base = (kt + 1) * 32;
#pragma unroll
            for (int ks = 0; ks < 2; ks++) {
                const int o = base + ks * 16;
                nxt[ks * 4 + 0] = *reinterpret_cast<const float2*>(a0 + o);
                nxt[ks * 4 + 1] = *reinterpret_cast<const float2*>(a1 + o);
                nxt[ks * 4 + 2] = *reinterpret_cast<const float2*>(a0 + o + 8);
                nxt[ks * 4 + 3] = *reinterpret_cast<const float2*>(a1 + o + 8);
            }
        }
#pragma unroll
        for (int ks = 0; ks < 2; ks++) {
            uint32_t ah[4], al[4];
#pragma unroll
            for (int j = 0; j < 4; j++)
                split_f2(cur[ks * 4 + j], ah[j], al[j]);
            const uint4* bp = g_bfrag + ((size_t)(kt * 2 + ks) * 8) * 32 + lane;
#pragma unroll
            for (int n8 = 0; n8 < 8; n8++) {
                const uint4 b = bp[n8 * 32];
                uint32_t bh[2] = {b.x, b.y};
                uint32_t bl[2] = {b.z, b.w};
                mma16816(acc[n8], ah, bh);
                mma16816(acc[n8], ah, bl);
                mma16816(acc[n8], al, bh);
            }
        }
#pragma unroll
        for (int j = 0; j < 8; j++) cur[j] = nxt[j];
    }

    // epilogue (same fragment->gmem mapping as validated R5 kernel)
    const int gid = lane >> 2;
    const int col = (lane & 3) * 2;
    const int row0 = bm0 + wid * 16 + gid;
#pragma unroll
    for (int n = 0; n < 8; n++) {
        *reinterpret_cast<float2*>(&g_logits[row0 * NE + n * 8 + col]) =
            make_float2(acc[n][0], acc[n][1]);
        *reinterpret_cast<float2*>(&g_logits[(row0 + 8) * NE + n * 8 + col]) =
            make_float2(acc[n][2], acc[n][3]);
    }
}

// ===================== top-C per expert (smem-cached radix select) ==========
__device__ __forceinline__ unsigned omap(float f) {
    unsigned u = __float_as_uint(f);
    return (u & 0x80000000u) ? ~u : (u | 0x80000000u);
}
__global__ void __launch_bounds__(256)
topk_kernel(float* __restrict__ routing)
{
    extern __shared__ unsigned keys[];          // TOK uints (64KB)
    __shared__ unsigned hist[256];
    __shared__ unsigned tlist[256];
    __shared__ unsigned s_pref, s_rem, s_tc;
    const int e = blockIdx.x, tid = threadIdx.x;

    for (int t = tid; t < TOK; t += 256)
        keys[t] = omap(g_logits[t * NE + e]);
    if (tid == 0) { s_pref = 0u; s_rem = CTOP; s_tc = 0u; }

    for (int b = 3; b >= 0; b--) {
        __syncthreads();
        hist[tid] = 0u;
        __syncthreads();
        const unsigned pref = s_pref;
        for (int t = tid; t < TOK; t += 256) {
            const unsigned u = keys[t];
            const bool ok = (b == 3) || ((u >> (((b + 1) & 3) * 8)) == pref);
            if (ok) atomicAdd(&hist[(u >> (b * 8)) & 255u], 1u);
        }
        __syncthreads();
        if (tid == 0) {
            unsigned rem = s_rem, cum = 0u;
            int d = 255;
            for (; d > 0; d--) { cum += hist[d]; if (cum >= rem) break; }
            if (cum < rem) { cum += hist[0]; d = 0; }
            s_rem = rem - (cum - hist[d]);
            s_pref = (pref << 8) | (unsigned)d;
        }
    }
    __syncthreads();
    const unsigned tkey = s_pref;
    for (int t = tid; t < TOK; t += 256) {
        const unsigned u = keys[t];
        float r = 0.f;
        if (u > tkey) r = 1.f;
        else if (u == tkey) {
            const unsigned p = atomicAdd(&s_tc, 1u);
            if (p < 256u) tlist[p] = (unsigned)t;
        }
        routing[(size_t)t * NE + e] = r;
    }
    __syncthreads();
    if (tid == 0) {
        int n = (int)s_tc; if (n > 256) n = 256;
        for (int i = 1; i < n; i++) {
            const unsigned v = tlist[i]; int j = i - 1;
            while (j >= 0 && tlist[j] > v) { tlist[j + 1] = tlist[j]; j--; }
            tlist[j + 1] = v;
        }
        int take = (int)s_rem; if (take > n) take = n;
        for (int i = 0; i < take; i++)
            routing[(size_t)tlist[i] * NE + e] = 1.f;
    }
}

// ============ softmax + mask + renorm; transposed block partials ============
__global__ void __launch_bounds__(256)
softmax_kernel(const float* __restrict__ routing, float* __restrict__ probs)
{
    const int lane = threadIdx.x & 31, w = threadIdx.x >> 5;
    const int t = blockIdx.x * 8 + w;
    __shared__ float sA[8][32], sB[8][32];

    const float l0 = g_logits[t * NE + lane];
    const float l1 = g_logits[t * NE + 32 + lane];
    float m = fmaxf(l0, l1);
#pragma unroll
    for (int o = 16; o; o >>= 1) m = fmaxf(m, __shfl_xor_sync(~0u, m, o));
    const float e0 = __expf(l0 - m), e1 = __expf(l1 - m);
    float s = e0 + e1;
#pragma unroll
    for (int o = 16; o; o >>= 1) s += __shfl_xor_sync(~0u, s, o);
    const float q0 = (e0 / s) * routing[(size_t)t * NE + lane];
    const float q1 = (e1 / s) * routing[(size_t)t * NE + 32 + lane];
    float rs = q0 + q1;
#pragma unroll
    for (int o = 16; o; o >>= 1) rs += __shfl_xor_sync(~0u, rs, o);
    const float inv = 1.f / (rs + EPSF);
    const float n0 = q0 * inv, n1 = q1 * inv;
    probs[(size_t)t * NE + lane] = n0;
    probs[(size_t)t * NE + 32 + lane] = n1;

    sA[w][lane] = n0; sB[w][lane] = n1;
    __syncthreads();
    if (w == 0) {
        float a = 0.f;
#pragma unroll
        for (int k = 0; k < 8; k++) a += sA[k][lane];
        g_partT[lane * NPART + blockIdx.x] = a;
    } else if (w == 1) {
        float a = 0.f;
#pragma unroll
        for (int k = 0; k < 8; k++) a += sB[k][lane];
        g_partT[(32 + lane) * NPART + blockIdx.x] = a;
    }
}

// ===================== aux loss (coalesced importance reduce) ===============
__global__ void __launch_bounds__(256)
imp_kernel()
{
    __shared__ float red[8];
    const int e = blockIdx.x, tid = threadIdx.x;
    float s = 0.f;
    for (int i = tid; i < NPART; i += 256) s += g_partT[e * NPART + i];
#pragma unroll
    for (int o = 16; o; o >>= 1) s += __shfl_xor_sync(~0u, s, o);
    if ((tid & 31) == 0) red[tid >> 5] = s;
    __syncthreads();
    if (tid == 0) {
        float a = 0.f;
#pragma unroll
        for (int k = 0; k < 8; k++) a += red[k];
        g_imp[e] = a;
    }
}
__global__ void __launch_bounds__(64)
loss_kernel(float* __restrict__ aux)
{
    __shared__ float v[64];
    v[threadIdx.x] = g_imp[threadIdx.x];
    __syncthreads();
    if (threadIdx.x == 0) {
        float m = 0.f;
        for (int i = 0; i < 64; i++) m += v[i];
        m *= (1.f / 64.f);
        float var = 0.f;
        for (int i = 0; i < 64; i++) { const float d = v[i] - m; var += d * d; }
        var *= (1.f / 63.f);
        const float r = sqrtf(var) / (m + EPSF);
        aux[0] = r * r;   // load std == 0 exactly -> load_loss == 0
    }
}

extern "C" void kernel_launch(void* const* d_in, const int* in_sizes, int n_in,
                              void* d_out, int out_size)
{
    const float* hidden = (const float*)d_in[0];
    const float* gate   = (const float*)d_in[1];
    float* probs   = (float*)d_out;
    float* routing = probs + (size_t)TOK * NE;
    float* aux     = routing + (size_t)TOK * NE;

    cudaFuncSetAttribute(topk_kernel,
                         cudaFuncAttributeMaxDynamicSharedMemorySize, TOK * 4);

    build_bfrag<<<256, 256>>>(gate);
    gemm_kernel<<<TOK / BM, 256>>>(hidden);
    topk_kernel<<<NE, 256, TOK * 4>>>(routing);
    softmax_kernel<<<TOK / 8, 256>>>(routing, probs);
    imp_kernel<<<NE, 256>>>();
    loss_kernel<<<1, 64>>>(aux);
}

// round 7
// speedup vs baseline: 1.8989x; 1.0094x over previous
#include <cuda_runtime.h>
#include <cuda_fp16.h>
#include <math.h>
#include <cstdint>

#define TOK  16384
#define HID  4096
#define NE   64
#define CTOP 512
#define EPSF 1e-6f

#define BM   128
#define NKT  (HID / 32)          // 128 k32 chunks
#define NPART 2048               // softmax blocks
#define STG  4                   // cp.async pipeline stages
#define STGU 512                 // uint4 entries per stage (8KB)

__device__ float g_logits[TOK * NE];
__device__ float g_partT[NE * NPART];   // transposed partials [e][blk]
__device__ float g_imp[NE];
__device__ uint4 g_bfrag[256 * 8 * 32]; // [k16][n8][lane] = {b0h,b1h,b0l,b1l}

// ---------------------------- helpers ---------------------------------------
__device__ __forceinline__ uint32_t smem_u32(const void* p) {
    uint32_t a;
    asm("{ .reg .u64 t; cvta.to.shared.u64 t, %1; cvt.u32.u64 %0, t; }"
        : "=r"(a) : "l"(p));
    return a;
}
__device__ __forceinline__ void cp16(uint32_t s, const void* g) {
    asm volatile("cp.async.cg.shared.global [%0], [%1], 16;" :: "r"(s), "l"(g));
}
#define CP_COMMIT() asm volatile("cp.async.commit_group;" ::: "memory")
#define CP_WAIT2()  asm volatile("cp.async.wait_group 2;" ::: "memory")
__device__ __forceinline__ void mma16816(float* c, const uint32_t* a,
                                         const uint32_t* b) {
    asm volatile(
        "mma.sync.aligned.m16n8k16.row.col.f32.f16.f16.f32 "
        "{%0,%1,%2,%3}, {%4,%5,%6,%7}, {%8,%9}, {%0,%1,%2,%3};"
        : "+f"(c[0]), "+f"(c[1]), "+f"(c[2]), "+f"(c[3])
        : "r"(a[0]), "r"(a[1]), "r"(a[2]), "r"(a[3]), "r"(b[0]), "r"(b[1]));
}
__device__ __forceinline__ void split_f2(float2 v, uint32_t& h, uint32_t& l) {
    __half2 hh = __floats2half2_rn(v.x, v.y);
    float2 hf = __half22float2(hh);
    __half2 ll = __floats2half2_rn(v.x - hf.x, v.y - hf.y);
    h = *reinterpret_cast<uint32_t*>(&hh);
    l = *reinterpret_cast<uint32_t*>(&ll);
}

// ------------- pre-kernel: gate_w -> fragment-replicated hi/lo halves -------
__global__ void __launch_bounds__(256)
build_bfrag(const float* __restrict__ gate)
{
    const int idx = blockIdx.x * 256 + threadIdx.x;  // 65536 total
    const int lane = idx & 31, n8 = (idx >> 5) & 7, k16 = idx >> 8;
    const int n = n8 * 8 + (lane >> 2);
    const int k0 = k16 * 16 + (lane & 3) * 2;
    const float* g = gate + (size_t)n * HID + k0;
    const float2 v0 = *reinterpret_cast<const float2*>(g);
    const float2 v1 = *reinterpret_cast<const float2*>(g + 8);
    uint32_t b0h, b0l, b1h, b1l;
    split_f2(v0, b0h, b0l);
    split_f2(v1, b1h, b1l);
    g_bfrag[idx] = make_uint4(b0h, b1h, b0l, b1l);
}

// ==== GEMM: logits = hidden @ gate_w^T (3xFP16 mma, cp.async B pipeline) ====
__global__ void __launch_bounds__(256, 1)
gemm_kernel(const float* __restrict__ A)
{
    extern __shared__ uint4 bsm[];      // STG * STGU uint4 = 32KB
    const int tid = threadIdx.x, lane = tid & 31, wid = tid >> 5;
    const int bm0 = blockIdx.x * BM;
    const int row = bm0 + wid * 16 + (lane >> 2);
    const uint32_t smb = smem_u32(bsm);

    const float* a0 = A + (size_t)row * HID + (lane & 3) * 2;
    const float* a1 = a0 + 8 * HID;

    float acc[8][4];
#pragma unroll
    for (int n = 0; n < 8; n++)
#pragma unroll
        for (int i = 0; i < 4; i++) acc[n][i] = 0.f;

    // prologue: issue B stages 0..2
#pragma unroll
    for (int kt = 0; kt < 3; kt++) {
        const uint32_t dst = smb + (uint32_t)(((kt & 3) * STGU + tid) * 16);
        const uint4* src = g_bfrag + (size_t)kt * STGU + tid;
        cp16(dst, src);
        cp16(dst + 256 * 16, src + 256);
        CP_COMMIT();
    }

    // prefetch kt=0 raw A
    float2 cur[8], nxt[8];
#pragma unroll
    for (int ks = 0; ks < 2; ks++) {
        const int o = ks * 16;
        cur[ks * 4 + 0] = *reinterpret_cast<const float2*>(a0 + o);
        cur[ks * 4 + 1] = *reinterpret_cast<const float2*>(a1 + o);
        cur[ks * 4 + 2] = *reinterpret_cast<const float2*>(a0 + o + 8);
        cur[ks * 4 + 3] = *reinterpret_cast<const float2*>(a1 + o + 8);
    }

#pragma unroll 1
    for (int kt = 0; kt < NKT; kt++) {
        if (kt + 1 < NKT) {
            const int base = (kt + 1) * 32;
#pragma unroll
            for (int ks = 0; ks < 2; ks++) {
                const int o = base + ks * 16;
                nxt[ks * 4 + 0] = *reinterpret_cast<const float2*>(a0 + o);
                nxt[ks * 4 + 1] = *reinterpret_cast<const float2*>(a1 + o);
                nxt[ks * 4 + 2] = *reinterpret_cast<const float2*>(a0 + o + 8);
                nxt[ks * 4 + 3] = *reinterpret_cast<const float2*>(a1 + o + 8);
            }
        }
        CP_WAIT2();
        __syncthreads();
        // issue stage kt+3 (safe: all warps finished consuming stage kt-1)
        if (kt + 3 < NKT) {
            const uint32_t dst = smb + (uint32_t)((((kt + 3) & 3) * STGU + tid) * 16);
            const uint4* src = g_bfrag + (size_t)(kt + 3) * STGU + tid;
            cp16(dst, src);
            cp16(dst + 256 * 16, src + 256);
        }
        CP_COMMIT();

        const uint32_t stage = smb + (uint32_t)((kt & 3) * STGU * 16);
#pragma unroll
        for (int ks = 0; ks < 2; ks++) {
            uint32_t ah[4], al[4];
#pragma unroll
            for (int j = 0; j < 4; j++)
                split_f2(cur[ks * 4 + j], ah[j], al[j]);
            const uint32_t bbase = stage + (uint32_t)(((ks * 8) * 32 + lane) * 16);
#pragma unroll
            for (int n8 = 0; n8 < 8; n8++) {
                uint4 b;
                asm volatile("ld.shared.v4.u32 {%0,%1,%2,%3}, [%4];"
                             : "=r"(b.x), "=r"(b.y), "=r"(b.z), "=r"(b.w)
                             : "r"(bbase + (uint32_t)(n8 * 32 * 16)));
                uint32_t bh[2] = {b.x, b.y};
                uint32_t bl[2] = {b.z, b.w};
                mma16816(acc[n8], ah, bh);
                mma16816(acc[n8], ah, bl);
                mma16816(acc[n8], al, bh);
            }
        }
#pragma unroll
        for (int j = 0; j < 8; j++) cur[j] = nxt[j];
    }

    // epilogue (same fragment->gmem mapping as validated R5/R6 kernels)
    const int gid = lane >> 2;
    const int col = (lane & 3) * 2;
    const int row0 = bm0 + wid * 16 + gid;
#pragma unroll
    for (int n = 0; n < 8; n++) {
        *reinterpret_cast<float2*>(&g_logits[row0 * NE + n * 8 + col]) =
            make_float2(acc[n][0], acc[n][1]);
        *reinterpret_cast<float2*>(&g_logits[(row0 + 8) * NE + n * 8 + col]) =
            make_float2(acc[n][2], acc[n][3]);
    }
}

// ===================== top-C per expert (smem-cached radix select) ==========
__device__ __forceinline__ unsigned omap(float f) {
    unsigned u = __float_as_uint(f);
    return (u & 0x80000000u) ? ~u : (u | 0x80000000u);
}
__global__ void __launch_bounds__(256)
topk_kernel(float* __restrict__ routing)
{
    extern __shared__ unsigned keys[];          // TOK uints (64KB)
    __shared__ unsigned hist[256];
    __shared__ unsigned tlist[256];
    __shared__ unsigned s_pref, s_rem, s_tc;
    const int e = blockIdx.x, tid = threadIdx.x;

    for (int t = tid; t < TOK; t += 256)
        keys[t] = omap(g_logits[t * NE + e]);
    if (tid == 0) { s_pref = 0u; s_rem = CTOP; s_tc = 0u; }

    for (int b = 3; b >= 0; b--) {
        __syncthreads();
        hist[tid] = 0u;
        __syncthreads();
        const unsigned pref = s_pref;
        for (int t = tid; t < TOK; t += 256) {
            const unsigned u = keys[t];
            const bool ok = (b == 3) || ((u >> (((b + 1) & 3) * 8)) == pref);
            if (ok) atomicAdd(&hist[(u >> (b * 8)) & 255u], 1u);
        }
        __syncthreads();
        if (tid == 0) {
            unsigned rem = s_rem, cum = 0u;
            int d = 255;
            for (; d > 0; d--) { cum += hist[d]; if (cum >= rem) break; }
            if (cum < rem) { cum += hist[0]; d = 0; }
            s_rem = rem - (cum - hist[d]);
            s_pref = (pref << 8) | (unsigned)d;
        }
    }
    __syncthreads();
    const unsigned tkey = s_pref;
    for (int t = tid; t < TOK; t += 256) {
        const unsigned u = keys[t];
        float r = 0.f;
        if (u > tkey) r = 1.f;
        else if (u == tkey) {
            const unsigned p = atomicAdd(&s_tc, 1u);
            if (p < 256u) tlist[p] = (unsigned)t;
        }
        routing[(size_t)t * NE + e] = r;
    }
    __syncthreads();
    if (tid == 0) {
        int n = (int)s_tc; if (n > 256) n = 256;
        for (int i = 1; i < n; i++) {
            const unsigned v = tlist[i]; int j = i - 1;
            while (j >= 0 && tlist[j] > v) { tlist[j + 1] = tlist[j]; j--; }
            tlist[j + 1] = v;
        }
        int take = (int)s_rem; if (take > n) take = n;
        for (int i = 0; i < take; i++)
            routing[(size_t)tlist[i] * NE + e] = 1.f;
    }
}

// ============ softmax + mask + renorm; transposed block partials ============
__global__ void __launch_bounds__(256)
softmax_kernel(const float* __restrict__ routing, float* __restrict__ probs)
{
    const int lane = threadIdx.x & 31, w = threadIdx.x >> 5;
    const int t = blockIdx.x * 8 + w;
    __shared__ float sA[8][32], sB[8][32];

    const float l0 = g_logits[t * NE + lane];
    const float l1 = g_logits[t * NE + 32 + lane];
    float m = fmaxf(l0, l1);
#pragma unroll
    for (int o = 16; o; o >>= 1) m = fmaxf(m, __shfl_xor_sync(~0u, m, o));
    const float e0 = __expf(l0 - m), e1 = __expf(l1 - m);
    float s = e0 + e1;
#pragma unroll
    for (int o = 16; o; o >>= 1) s += __shfl_xor_sync(~0u, s, o);
    const float q0 = (e0 / s) * routing[(size_t)t * NE + lane];
    const float q1 = (e1 / s) * routing[(size_t)t * NE + 32 + lane];
    float rs = q0 + q1;
#pragma unroll
    for (int o = 16; o; o >>= 1) rs += __shfl_xor_sync(~0u, rs, o);
    const float inv = 1.f / (rs + EPSF);
    const float n0 = q0 * inv, n1 = q1 * inv;
    probs[(size_t)t * NE + lane] = n0;
    probs[(size_t)t * NE + 32 + lane] = n1;

    sA[w][lane] = n0; sB[w][lane] = n1;
    __syncthreads();
    if (w == 0) {
        float a = 0.f;
#pragma unroll
        for (int k = 0; k < 8; k++) a += sA[k][lane];
        g_partT[lane * NPART + blockIdx.x] = a;
    } else if (w == 1) {
        float a = 0.f;
#pragma unroll
        for (int k = 0; k < 8; k++) a += sB[k][lane];
        g_partT[(32 + lane) * NPART + blockIdx.x] = a;
    }
}

// ===================== aux loss (coalesced importance reduce) ===============
__global__ void __launch_bounds__(256)
imp_kernel()
{
    __shared__ float red[8];
    const int e = blockIdx.x, tid = threadIdx.x;
    float s = 0.f;
    for (int i = tid; i < NPART; i += 256) s += g_partT[e * NPART + i];
#pragma unroll
    for (int o = 16; o; o >>= 1) s += __shfl_xor_sync(~0u, s, o);
    if ((tid & 31) == 0) red[tid >> 5] = s;
    __syncthreads();
    if (tid == 0) {
        float a = 0.f;
#pragma unroll
        for (int k = 0; k < 8; k++) a += red[k];
        g_imp[e] = a;
    }
}
__global__ void __launch_bounds__(64)
loss_kernel(float* __restrict__ aux)
{
    __shared__ float v[64];
    v[threadIdx.x] = g_imp[threadIdx.x];
    __syncthreads();
    if (threadIdx.x == 0) {
        float m = 0.f;
        for (int i = 0; i < 64; i++) m += v[i];
        m *= (1.f / 64.f);
        float var = 0.f;
        for (int i = 0; i < 64; i++) { const float d = v[i] - m; var += d * d; }
        var *= (1.f / 63.f);
        const float r = sqrtf(var) / (m + EPSF);
        aux[0] = r * r;   // load std == 0 exactly -> load_loss == 0
    }
}

extern "C" void kernel_launch(void* const* d_in, const int* in_sizes, int n_in,
                              void* d_out, int out_size)
{
    const float* hidden = (const float*)d_in[0];
    const float* gate   = (const float*)d_in[1];
    float* probs   = (float*)d_out;
    float* routing = probs + (size_t)TOK * NE;
    float* aux     = routing + (size_t)TOK * NE;

    cudaFuncSetAttribute(topk_kernel,
                         cudaFuncAttributeMaxDynamicSharedMemorySize, TOK * 4);

    build_bfrag<<<256, 256>>>(gate);
    gemm_kernel<<<TOK / BM, 256, STG * STGU * 16>>>(hidden);
    topk_kernel<<<NE, 256, TOK * 4>>>(routing);
    softmax_kernel<<<TOK / 8, 256>>>(routing, probs);
    imp_kernel<<<NE, 256>>>();
    loss_kernel<<<1, 64>>>(aux);
}